// round 15
// baseline (speedup 1.0000x reference)
#include <cuda_runtime.h>
#include <cuda_fp16.h>
#include <cstdint>

// ---------------------------------------------------------------------------
// VS_LightGCN: 3-layer LightGCN propagation + dot-product readout.
//   N = 300000, D = 64, NNZ = 5e6, ALPHA = 0.5
//   Ek = SpMM(A, E_{k-1}) + 0.5*emb0     (E0 = cat(user_emb, item_emb))
//   light = (E0 + 3E1 + 2E2 + E3)/4 ;  gamma[b] = <light[u], light[N_USERS+i]>
//
// R15: R14 + 4-edge unrolled SpMM with int4 edge loads and 4 independent
// accumulator chains (gather MLP 2 -> 4; spmm measured latency-bound).
// ---------------------------------------------------------------------------

#define N_USERS 100000
#define N_ITEMS 200000
#define N_NODES (N_USERS + N_ITEMS)
#define DIM     64
#define DIMH2   32           // half2 / float2 chunks per row
#define MAX_Q   8192         // max unique query rows (2*B)
#define CAP     64           // bucket capacity per row (P(deg>64) ~ 0)
#define CAPSH   6            // log2(CAP)

// ---- static device scratch (no allocations allowed) -----------------------
__device__ __half g_H0[(size_t)N_NODES * DIM];   // fp16 concat(E0)
__device__ __half g_H1[(size_t)N_NODES * DIM];   // fp16 E1 (layer-1 gather)
__device__ __half g_H2[(size_t)N_NODES * DIM];   // fp16 E2 (layer-2 gather)
__device__ float  g_F1[MAX_Q * DIM];             // fp32 E1 at query rows
__device__ float  g_F2[MAX_Q * DIM];             // fp32 E2 at query rows
__device__ float  g_F3[MAX_Q * DIM];             // fp32 E3 at query rows
__device__ int   g_cnt[N_NODES];                 // per-row edge count
__device__ int2  g_edge[(size_t)N_NODES * CAP];  // bucketed {col, bits(val)}
__device__ unsigned char g_flag2[N_NODES];       // E2 rows needed downstream
__device__ int   g_flag3[N_NODES];               // query rows (atomicExch)
__device__ int   g_slot3[N_NODES];               // row -> compact slot
__device__ int   g_work3[MAX_Q];                 // compact list of query rows
__device__ int   g_nwork3;

// ---------------------------------------------------------------------------
// 0) fused: convert fp32 concat -> fp16 g_H0  AND  zero counters/flags.
// ---------------------------------------------------------------------------
__global__ void k_convert_zero(const float2* __restrict__ ue,
                               const float2* __restrict__ ie)
{
    int j = blockIdx.x * blockDim.x + threadIdx.x;
    const int total = N_NODES * DIMH2;      // 9.6M
    if (j < total) {
        int n = j >> 5;                      // node (DIMH2 == 32)
        float2 v = (n < N_USERS) ? __ldg(&ue[j])
                                 : __ldg(&ie[j - N_USERS * DIMH2]);
        reinterpret_cast<__half2*>(g_H0)[j] = __float22half2_rn(v);
    }
    if (j < N_NODES) {
        g_cnt[j]   = 0;
        g_flag2[j] = 0;
        g_flag3[j] = 0;
    }
    if (j == 0) g_nwork3 = 0;
}

// ---------------------------------------------------------------------------
// 1) mark query nodes: flag3 + dedup worklist + slot map; flag2 at queries
// ---------------------------------------------------------------------------
__global__ void k_mark_queries(const int* __restrict__ users,
                               const int* __restrict__ items, int B)
{
    int b = blockIdx.x * blockDim.x + threadIdx.x;
    if (b >= B) return;
    int u = __ldg(users + b);
    int i = N_USERS + __ldg(items + b);
    g_flag2[u] = 1;
    g_flag2[i] = 1;
    if (atomicExch(&g_flag3[u], 1) == 0) {
        int p = atomicAdd(&g_nwork3, 1);
        g_work3[p] = u;
        g_slot3[u] = p;
    }
    if (atomicExch(&g_flag3[i], 1) == 0) {
        int p = atomicAdd(&g_nwork3, 1);
        g_work3[p] = i;
        g_slot3[i] = p;
    }
}

// ---------------------------------------------------------------------------
// 2) scatter edges into fixed-capacity row buckets (4 edges/thread).
//    Counts produced here — no histogram / scan pass needed.
// ---------------------------------------------------------------------------
__global__ void k_scatter(const int*   __restrict__ rows,
                          const int*   __restrict__ cols,
                          const float* __restrict__ vals, int nnz)
{
    int t = blockIdx.x * blockDim.x + threadIdx.x;
    int e0 = t * 4;
    if (e0 + 3 < nnz) {
        int4   r = __ldg((const int4*)(rows + e0));
        int4   c = __ldg((const int4*)(cols + e0));
        float4 v = __ldg((const float4*)(vals + e0));
        int p0 = atomicAdd(&g_cnt[r.x], 1);
        int p1 = atomicAdd(&g_cnt[r.y], 1);
        int p2 = atomicAdd(&g_cnt[r.z], 1);
        int p3 = atomicAdd(&g_cnt[r.w], 1);
        if (p0 < CAP) g_edge[((size_t)r.x << CAPSH) + p0] = make_int2(c.x, __float_as_int(v.x));
        if (p1 < CAP) g_edge[((size_t)r.y << CAPSH) + p1] = make_int2(c.y, __float_as_int(v.y));
        if (p2 < CAP) g_edge[((size_t)r.z << CAPSH) + p2] = make_int2(c.z, __float_as_int(v.z));
        if (p3 < CAP) g_edge[((size_t)r.w << CAPSH) + p3] = make_int2(c.w, __float_as_int(v.w));
    } else {
        for (int e = e0; e < nnz; e++) {
            int r = rows[e];
            int p = atomicAdd(&g_cnt[r], 1);
            if (p < CAP)
                g_edge[((size_t)r << CAPSH) + p] =
                    make_int2(cols[e], __float_as_int(vals[e]));
        }
    }
}

// ---------------------------------------------------------------------------
// 3) Row-parallel SpMM: warp per row, lane owns one half2 (2 dims) of D.
//    fp16 gather, fp32 accumulate. 4-edge unroll, int4 edge loads,
//    4 independent accumulator chains (gather MLP = 4).
// ---------------------------------------------------------------------------
template <int LAYER>
__device__ __forceinline__ float2 spmm_row(int row, int lane,
                                           const float2* __restrict__ ue0,
                                           const float2* __restrict__ ie0)
{
    const __half2* in = reinterpret_cast<const __half2*>(
        (LAYER == 0) ? g_H0 : (LAYER == 1) ? g_H1 : g_H2);

    const int2* ep = g_edge + ((size_t)row << CAPSH);   // 512B-aligned base
    int cnt = __ldg(&g_cnt[row]);
    cnt = (cnt > CAP) ? CAP : cnt;

    float2 r0 = (row < N_USERS)
        ? __ldg(&ue0[(size_t)row * DIMH2 + lane])
        : __ldg(&ie0[(size_t)(row - N_USERS) * DIMH2 + lane]);
    float2 a0 = make_float2(0.5f * r0.x, 0.5f * r0.y);
    float2 a1 = make_float2(0.0f, 0.0f);
    float2 a2 = make_float2(0.0f, 0.0f);
    float2 a3 = make_float2(0.0f, 0.0f);

    int j = 0;
    for (; j + 4 <= cnt; j += 4) {
        // two int4 loads fetch 4 edges (pairs 16B-aligned: base 512B, j%4==0)
        int4 ea = __ldg((const int4*)(ep + j));       // edges j, j+1
        int4 eb = __ldg((const int4*)(ep + j + 2));   // edges j+2, j+3
        float2 g0 = __half22float2(__ldg(in + (size_t)ea.x * DIMH2 + lane));
        float2 g1 = __half22float2(__ldg(in + (size_t)ea.z * DIMH2 + lane));
        float2 g2 = __half22float2(__ldg(in + (size_t)eb.x * DIMH2 + lane));
        float2 g3 = __half22float2(__ldg(in + (size_t)eb.z * DIMH2 + lane));
        float v0 = __int_as_float(ea.y);
        float v1 = __int_as_float(ea.w);
        float v2 = __int_as_float(eb.y);
        float v3 = __int_as_float(eb.w);
        a0.x = fmaf(v0, g0.x, a0.x);  a0.y = fmaf(v0, g0.y, a0.y);
        a1.x = fmaf(v1, g1.x, a1.x);  a1.y = fmaf(v1, g1.y, a1.y);
        a2.x = fmaf(v2, g2.x, a2.x);  a2.y = fmaf(v2, g2.y, a2.y);
        a3.x = fmaf(v3, g3.x, a3.x);  a3.y = fmaf(v3, g3.y, a3.y);
    }
    for (; j < cnt; j++) {
        int2 e0 = __ldg(ep + j);
        float2 g0 = __half22float2(__ldg(in + (size_t)e0.x * DIMH2 + lane));
        float v0 = __int_as_float(e0.y);
        a0.x = fmaf(v0, g0.x, a0.x);
        a0.y = fmaf(v0, g0.y, a0.y);
    }
    a0.x += a1.x; a0.y += a1.y;
    a2.x += a3.x; a2.y += a3.y;
    a0.x += a2.x; a0.y += a2.y;
    return a0;
}

template <int LAYER>   // LAYER 0 -> H1 (+F1@query), LAYER 1 -> H2 (+F2@query)
__global__ void __launch_bounds__(256)
k_spmm_csr(const float2* __restrict__ ue0, const float2* __restrict__ ie0)
{
    int w    = (blockIdx.x * blockDim.x + threadIdx.x) >> 5;
    int lane = threadIdx.x & 31;
    if (w >= N_NODES) return;
    if (LAYER == 1 && !g_flag2[w]) return;

    float2 acc = spmm_row<LAYER>(w, lane, ue0, ie0);

    __half2* out = reinterpret_cast<__half2*>((LAYER == 0) ? g_H1 : g_H2);
    out[(size_t)w * DIMH2 + lane] = __float22half2_rn(acc);

    if (g_flag3[w]) {   // fp32 side-copy for the epilogue
        float2* f = reinterpret_cast<float2*>((LAYER == 0) ? g_F1 : g_F2);
        f[(size_t)g_slot3[w] * DIMH2 + lane] = acc;
    }
}

// ---------------------------------------------------------------------------
// 4) flag2 from buckets: for each query row, mark its in-neighbors.
// ---------------------------------------------------------------------------
__global__ void k_flag2()
{
    int w    = (blockIdx.x * blockDim.x + threadIdx.x) >> 5;
    int lane = threadIdx.x & 31;
    if (w >= g_nwork3) return;
    int row = g_work3[w];
    int cnt = __ldg(&g_cnt[row]);
    cnt = (cnt > CAP) ? CAP : cnt;
    const int2* ep = g_edge + ((size_t)row << CAPSH);
    for (int j = lane; j < cnt; j += 32)
        g_flag2[ep[j].x] = 1;
}

// Layer 2 over the compact worklist (<= MAX_Q rows); fp32 output only.
__global__ void __launch_bounds__(256)
k_spmm_l3(const float2* __restrict__ ue0, const float2* __restrict__ ie0)
{
    int w    = (blockIdx.x * blockDim.x + threadIdx.x) >> 5;
    int lane = threadIdx.x & 31;
    if (w >= g_nwork3) return;
    int row = g_work3[w];
    float2 acc = spmm_row<2>(row, lane, ue0, ie0);
    reinterpret_cast<float2*>(g_F3)[(size_t)w * DIMH2 + lane] = acc;  // slot == w
}

// ---------------------------------------------------------------------------
// 5) Epilogue: warp per output b. All reads fp32 (E0 tables + compact F1..F3).
// ---------------------------------------------------------------------------
__global__ void k_epilogue(const int* __restrict__ users,
                           const int* __restrict__ items,
                           const float* __restrict__ user_emb,
                           const float* __restrict__ item_emb,
                           float* __restrict__ out, int B)
{
    int t = blockIdx.x * blockDim.x + threadIdx.x;
    int b = t >> 5;
    int lane = t & 31;
    if (b >= B) return;

    int u = __ldg(users + b);
    int i = N_USERS + __ldg(items + b);
    int su = __ldg(&g_slot3[u]);
    int si = __ldg(&g_slot3[i]);

    float s = 0.0f;
#pragma unroll
    for (int k = 0; k < 2; k++) {
        int d = lane + 32 * k;
        size_t uo = (size_t)su * DIM + d;
        size_t io = (size_t)si * DIM + d;

        float cu = user_emb[(size_t)u * DIM + d];   // u always < N_USERS
        float ci = item_emb[(size_t)(i - N_USERS) * DIM + d];

        float lu = (cu + 3.0f * g_F1[uo] + 2.0f * g_F2[uo] + g_F3[uo]) * 0.25f;
        float li = (ci + 3.0f * g_F1[io] + 2.0f * g_F2[io] + g_F3[io]) * 0.25f;
        s = fmaf(lu, li, s);
    }
#pragma unroll
    for (int o = 16; o > 0; o >>= 1)
        s += __shfl_xor_sync(0xffffffffu, s, o);
    if (lane == 0) out[b] = s;
}

// ---------------------------------------------------------------------------
// kernel_launch — stream-ordered, graph-capturable, allocation-free.
// Order: (0) convert_zero (1) mark (2) scatter (3) spmm0 <- profiled index
//        (4) flag2 (5) spmm1 (6) spmm_l3 (7) epilogue
// Inputs: users, items, rows, cols, vals, user_emb, item_emb, user_emb0, item_emb0
// ---------------------------------------------------------------------------
extern "C" void kernel_launch(void* const* d_in, const int* in_sizes, int n_in,
                              void* d_out, int out_size)
{
    const int*   users     = (const int*)  d_in[0];
    const int*   items     = (const int*)  d_in[1];
    const int*   rows      = (const int*)  d_in[2];
    const int*   cols      = (const int*)  d_in[3];
    const float* vals      = (const float*)d_in[4];
    const float* user_emb  = (const float*)d_in[5];
    const float* item_emb  = (const float*)d_in[6];
    const float* user_emb0 = (const float*)d_in[7];
    const float* item_emb0 = (const float*)d_in[8];
    float*       out       = (float*)d_out;

    const int nnz = in_sizes[2];
    const int B   = in_sizes[0];

    // (0) fused convert + zero
    {
        int total = N_NODES * DIMH2;
        k_convert_zero<<<(total + 255) / 256, 256>>>((const float2*)user_emb,
                                                     (const float2*)item_emb);
    }
    // (1) mark queries
    k_mark_queries<<<(B + 255) / 256, 256>>>(users, items, B);
    // (2) bucket scatter (builds counts too)
    {
        int nt4 = (nnz + 3) / 4;
        k_scatter<<<(nt4 + 255) / 256, 256>>>(rows, cols, vals, nnz);
    }
    // (3) layer-0 SpMM  <- ncu profiled launch
    int spmm_blocks = (N_NODES + 7) / 8;
    k_spmm_csr<0><<<spmm_blocks, 256>>>((const float2*)user_emb0,
                                        (const float2*)item_emb0);
    // (4) flag2 (needed by layer-1 only)
    k_flag2<<<(MAX_Q * 32 + 255) / 256, 256>>>();
    // (5) layer-1 SpMM (pruned)
    k_spmm_csr<1><<<spmm_blocks, 256>>>((const float2*)user_emb0,
                                        (const float2*)item_emb0);
    // (6) layer-2 SpMM over compact worklist
    k_spmm_l3<<<(MAX_Q * 32 + 255) / 256, 256>>>((const float2*)user_emb0,
                                                 (const float2*)item_emb0);
    // (7) readout
    k_epilogue<<<(B * 32 + 255) / 256, 256>>>(users, items, user_emb, item_emb,
                                              out, B);
}

// round 16
// speedup vs baseline: 1.0491x; 1.0491x over previous
#include <cuda_runtime.h>
#include <cuda_fp16.h>
#include <cstdint>

// ---------------------------------------------------------------------------
// VS_LightGCN: 3-layer LightGCN propagation + dot-product readout.
//   N = 300000, D = 64, NNZ = 5e6, ALPHA = 0.5
//   Ek = SpMM(A, E_{k-1}) + 0.5*emb0     (E0 = cat(user_emb, item_emb))
//   light = (E0 + 3E1 + 2E2 + E3)/4 ;  gamma[b] = <light[u], light[N_USERS+i]>
//
// R16: R14 baseline (2-edge SpMM, bucket scatter) + 512-thread SpMM blocks
// (halve CTAs/SM -> less cross-CTA L1tex-queue spread) + dedup worklist for
// the layer-1 row set (packed active warps).
// ---------------------------------------------------------------------------

#define N_USERS 100000
#define N_ITEMS 200000
#define N_NODES (N_USERS + N_ITEMS)
#define DIM     64
#define DIMH2   32           // half2 / float2 chunks per row
#define MAX_Q   8192         // max unique query rows (2*B)
#define CAP     64           // bucket capacity per row (P(deg>64) ~ 0)
#define CAPSH   6            // log2(CAP)

#define SPMM_THREADS 512     // 16 warps/block
#define SPMM_WPB     (SPMM_THREADS / 32)

// ---- static device scratch (no allocations allowed) -----------------------
__device__ __half g_H0[(size_t)N_NODES * DIM];   // fp16 concat(E0)
__device__ __half g_H1[(size_t)N_NODES * DIM];   // fp16 E1 (layer-1 gather)
__device__ __half g_H2[(size_t)N_NODES * DIM];   // fp16 E2 (layer-2 gather)
__device__ float  g_F1[MAX_Q * DIM];             // fp32 E1 at query rows
__device__ float  g_F2[MAX_Q * DIM];             // fp32 E2 at query rows
__device__ float  g_F3[MAX_Q * DIM];             // fp32 E3 at query rows
__device__ int   g_cnt[N_NODES];                 // per-row edge count
__device__ int2  g_edge[(size_t)N_NODES * CAP];  // bucketed {col, bits(val)}
__device__ int   g_flag2[N_NODES];               // E2-needed (atomicExch dedup)
__device__ int   g_flag3[N_NODES];               // query rows (atomicExch)
__device__ int   g_slot3[N_NODES];               // row -> compact F slot
__device__ int   g_work3[MAX_Q];                 // compact list of query rows
__device__ int   g_nwork3;
__device__ int   g_work2[N_NODES];               // compact list of E2 rows
__device__ int   g_nwork2;

// ---------------------------------------------------------------------------
// 0) fused: convert fp32 concat -> fp16 g_H0  AND  zero counters/flags.
// ---------------------------------------------------------------------------
__global__ void k_convert_zero(const float2* __restrict__ ue,
                               const float2* __restrict__ ie)
{
    int j = blockIdx.x * blockDim.x + threadIdx.x;
    const int total = N_NODES * DIMH2;      // 9.6M
    if (j < total) {
        int n = j >> 5;                      // node (DIMH2 == 32)
        float2 v = (n < N_USERS) ? __ldg(&ue[j])
                                 : __ldg(&ie[j - N_USERS * DIMH2]);
        reinterpret_cast<__half2*>(g_H0)[j] = __float22half2_rn(v);
    }
    if (j < N_NODES) {
        g_cnt[j]   = 0;
        g_flag2[j] = 0;
        g_flag3[j] = 0;
    }
    if (j == 0) { g_nwork3 = 0; g_nwork2 = 0; }
}

// ---------------------------------------------------------------------------
// 1) mark query nodes: flag3 worklist (F slots) + seed the E2 worklist
// ---------------------------------------------------------------------------
__global__ void k_mark_queries(const int* __restrict__ users,
                               const int* __restrict__ items, int B)
{
    int b = blockIdx.x * blockDim.x + threadIdx.x;
    if (b >= B) return;
    int u = __ldg(users + b);
    int i = N_USERS + __ldg(items + b);
    if (atomicExch(&g_flag3[u], 1) == 0) {
        int p = atomicAdd(&g_nwork3, 1);
        g_work3[p] = u;
        g_slot3[u] = p;
    }
    if (atomicExch(&g_flag3[i], 1) == 0) {
        int p = atomicAdd(&g_nwork3, 1);
        g_work3[p] = i;
        g_slot3[i] = p;
    }
    if (atomicExch(&g_flag2[u], 1) == 0)
        g_work2[atomicAdd(&g_nwork2, 1)] = u;
    if (atomicExch(&g_flag2[i], 1) == 0)
        g_work2[atomicAdd(&g_nwork2, 1)] = i;
}

// ---------------------------------------------------------------------------
// 2) scatter edges into fixed-capacity row buckets (4 edges/thread).
// ---------------------------------------------------------------------------
__global__ void k_scatter(const int*   __restrict__ rows,
                          const int*   __restrict__ cols,
                          const float* __restrict__ vals, int nnz)
{
    int t = blockIdx.x * blockDim.x + threadIdx.x;
    int e0 = t * 4;
    if (e0 + 3 < nnz) {
        int4   r = __ldg((const int4*)(rows + e0));
        int4   c = __ldg((const int4*)(cols + e0));
        float4 v = __ldg((const float4*)(vals + e0));
        int p0 = atomicAdd(&g_cnt[r.x], 1);
        int p1 = atomicAdd(&g_cnt[r.y], 1);
        int p2 = atomicAdd(&g_cnt[r.z], 1);
        int p3 = atomicAdd(&g_cnt[r.w], 1);
        if (p0 < CAP) g_edge[((size_t)r.x << CAPSH) + p0] = make_int2(c.x, __float_as_int(v.x));
        if (p1 < CAP) g_edge[((size_t)r.y << CAPSH) + p1] = make_int2(c.y, __float_as_int(v.y));
        if (p2 < CAP) g_edge[((size_t)r.z << CAPSH) + p2] = make_int2(c.z, __float_as_int(v.z));
        if (p3 < CAP) g_edge[((size_t)r.w << CAPSH) + p3] = make_int2(c.w, __float_as_int(v.w));
    } else {
        for (int e = e0; e < nnz; e++) {
            int r = rows[e];
            int p = atomicAdd(&g_cnt[r], 1);
            if (p < CAP)
                g_edge[((size_t)r << CAPSH) + p] =
                    make_int2(cols[e], __float_as_int(vals[e]));
        }
    }
}

// ---------------------------------------------------------------------------
// 3) Row-parallel SpMM core: warp per row, lane owns one half2 of D.
//    fp16 gather, fp32 accumulate, 2-edge unroll (R14-proven form).
// ---------------------------------------------------------------------------
template <int LAYER>
__device__ __forceinline__ float2 spmm_row(int row, int lane,
                                           const float2* __restrict__ ue0,
                                           const float2* __restrict__ ie0)
{
    const __half2* in = reinterpret_cast<const __half2*>(
        (LAYER == 0) ? g_H0 : (LAYER == 1) ? g_H1 : g_H2);

    const int2* ep = g_edge + ((size_t)row << CAPSH);
    int cnt = __ldg(&g_cnt[row]);
    cnt = (cnt > CAP) ? CAP : cnt;

    float2 r0 = (row < N_USERS)
        ? __ldg(&ue0[(size_t)row * DIMH2 + lane])
        : __ldg(&ie0[(size_t)(row - N_USERS) * DIMH2 + lane]);
    float2 acc0 = make_float2(0.5f * r0.x, 0.5f * r0.y);
    float2 acc1 = make_float2(0.0f, 0.0f);

    int j = 0;
    for (; j + 2 <= cnt; j += 2) {
        int2 e0 = __ldg(ep + j);
        int2 e1 = __ldg(ep + j + 1);
        float2 g0 = __half22float2(__ldg(in + (size_t)e0.x * DIMH2 + lane));
        float2 g1 = __half22float2(__ldg(in + (size_t)e1.x * DIMH2 + lane));
        float v0 = __int_as_float(e0.y);
        float v1 = __int_as_float(e1.y);
        acc0.x = fmaf(v0, g0.x, acc0.x);
        acc0.y = fmaf(v0, g0.y, acc0.y);
        acc1.x = fmaf(v1, g1.x, acc1.x);
        acc1.y = fmaf(v1, g1.y, acc1.y);
    }
    if (j < cnt) {
        int2 e0 = __ldg(ep + j);
        float2 g0 = __half22float2(__ldg(in + (size_t)e0.x * DIMH2 + lane));
        float v0 = __int_as_float(e0.y);
        acc0.x = fmaf(v0, g0.x, acc0.x);
        acc0.y = fmaf(v0, g0.y, acc0.y);
    }
    acc0.x += acc1.x;
    acc0.y += acc1.y;
    return acc0;
}

// Layer 0: all rows -> H1 (+F1 at query rows). 512-thread blocks.
__global__ void __launch_bounds__(SPMM_THREADS)
k_spmm0(const float2* __restrict__ ue0, const float2* __restrict__ ie0)
{
    int w    = (blockIdx.x * blockDim.x + threadIdx.x) >> 5;
    int lane = threadIdx.x & 31;
    if (w >= N_NODES) return;

    float2 acc = spmm_row<0>(w, lane, ue0, ie0);

    reinterpret_cast<__half2*>(g_H1)[(size_t)w * DIMH2 + lane] =
        __float22half2_rn(acc);
    if (g_flag3[w]) {
        reinterpret_cast<float2*>(g_F1)[(size_t)g_slot3[w] * DIMH2 + lane] = acc;
    }
}

// ---------------------------------------------------------------------------
// 4) extend E2 worklist with in-neighbors of query rows (dedup).
// ---------------------------------------------------------------------------
__global__ void k_flag2()
{
    int w    = (blockIdx.x * blockDim.x + threadIdx.x) >> 5;
    int lane = threadIdx.x & 31;
    if (w >= g_nwork3) return;
    int row = g_work3[w];
    int cnt = __ldg(&g_cnt[row]);
    cnt = (cnt > CAP) ? CAP : cnt;
    const int2* ep = g_edge + ((size_t)row << CAPSH);
    for (int j = lane; j < cnt; j += 32) {
        int c = ep[j].x;
        if (atomicExch(&g_flag2[c], 1) == 0)
            g_work2[atomicAdd(&g_nwork2, 1)] = c;
    }
}

// Layer 1: worklist rows -> H2 (+F2 at query rows). 512-thread blocks.
__global__ void __launch_bounds__(SPMM_THREADS)
k_spmm1(const float2* __restrict__ ue0, const float2* __restrict__ ie0)
{
    int w    = (blockIdx.x * blockDim.x + threadIdx.x) >> 5;
    int lane = threadIdx.x & 31;
    if (w >= g_nwork2) return;
    int row = g_work2[w];

    float2 acc = spmm_row<1>(row, lane, ue0, ie0);

    reinterpret_cast<__half2*>(g_H2)[(size_t)row * DIMH2 + lane] =
        __float22half2_rn(acc);
    if (g_flag3[row]) {
        reinterpret_cast<float2*>(g_F2)[(size_t)g_slot3[row] * DIMH2 + lane] = acc;
    }
}

// Layer 2 over the query worklist (<= MAX_Q rows); fp32 output only.
__global__ void __launch_bounds__(256)
k_spmm_l3(const float2* __restrict__ ue0, const float2* __restrict__ ie0)
{
    int w    = (blockIdx.x * blockDim.x + threadIdx.x) >> 5;
    int lane = threadIdx.x & 31;
    if (w >= g_nwork3) return;
    int row = g_work3[w];
    float2 acc = spmm_row<2>(row, lane, ue0, ie0);
    reinterpret_cast<float2*>(g_F3)[(size_t)w * DIMH2 + lane] = acc;  // slot == w
}

// ---------------------------------------------------------------------------
// 5) Epilogue: warp per output b. All reads fp32 (E0 tables + compact F1..F3).
// ---------------------------------------------------------------------------
__global__ void k_epilogue(const int* __restrict__ users,
                           const int* __restrict__ items,
                           const float* __restrict__ user_emb,
                           const float* __restrict__ item_emb,
                           float* __restrict__ out, int B)
{
    int t = blockIdx.x * blockDim.x + threadIdx.x;
    int b = t >> 5;
    int lane = t & 31;
    if (b >= B) return;

    int u = __ldg(users + b);
    int i = N_USERS + __ldg(items + b);
    int su = __ldg(&g_slot3[u]);
    int si = __ldg(&g_slot3[i]);

    float s = 0.0f;
#pragma unroll
    for (int k = 0; k < 2; k++) {
        int d = lane + 32 * k;
        size_t uo = (size_t)su * DIM + d;
        size_t io = (size_t)si * DIM + d;

        float cu = user_emb[(size_t)u * DIM + d];   // u always < N_USERS
        float ci = item_emb[(size_t)(i - N_USERS) * DIM + d];

        float lu = (cu + 3.0f * g_F1[uo] + 2.0f * g_F2[uo] + g_F3[uo]) * 0.25f;
        float li = (ci + 3.0f * g_F1[io] + 2.0f * g_F2[io] + g_F3[io]) * 0.25f;
        s = fmaf(lu, li, s);
    }
#pragma unroll
    for (int o = 16; o > 0; o >>= 1)
        s += __shfl_xor_sync(0xffffffffu, s, o);
    if (lane == 0) out[b] = s;
}

// ---------------------------------------------------------------------------
// kernel_launch — stream-ordered, graph-capturable, allocation-free.
// Order: (0) convert_zero (1) mark (2) scatter (3) spmm0 <- profiled index
//        (4) flag2 (5) spmm1 (6) spmm_l3 (7) epilogue
// Inputs: users, items, rows, cols, vals, user_emb, item_emb, user_emb0, item_emb0
// ---------------------------------------------------------------------------
extern "C" void kernel_launch(void* const* d_in, const int* in_sizes, int n_in,
                              void* d_out, int out_size)
{
    const int*   users     = (const int*)  d_in[0];
    const int*   items     = (const int*)  d_in[1];
    const int*   rows      = (const int*)  d_in[2];
    const int*   cols      = (const int*)  d_in[3];
    const float* vals      = (const float*)d_in[4];
    const float* user_emb  = (const float*)d_in[5];
    const float* item_emb  = (const float*)d_in[6];
    const float* user_emb0 = (const float*)d_in[7];
    const float* item_emb0 = (const float*)d_in[8];
    float*       out       = (float*)d_out;

    const int nnz = in_sizes[2];
    const int B   = in_sizes[0];

    // (0) fused convert + zero
    {
        int total = N_NODES * DIMH2;
        k_convert_zero<<<(total + 255) / 256, 256>>>((const float2*)user_emb,
                                                     (const float2*)item_emb);
    }
    // (1) mark queries (seeds work2 + work3)
    k_mark_queries<<<(B + 255) / 256, 256>>>(users, items, B);
    // (2) bucket scatter (builds counts too)
    {
        int nt4 = (nnz + 3) / 4;
        k_scatter<<<(nt4 + 255) / 256, 256>>>(rows, cols, vals, nnz);
    }
    // (3) layer-0 SpMM, 512-thread blocks  <- ncu profiled launch
    {
        int blocks = (N_NODES + SPMM_WPB - 1) / SPMM_WPB;
        k_spmm0<<<blocks, SPMM_THREADS>>>((const float2*)user_emb0,
                                          (const float2*)item_emb0);
    }
    // (4) extend E2 worklist with query-row neighbors
    k_flag2<<<(MAX_Q * 32 + 255) / 256, 256>>>();
    // (5) layer-1 SpMM over packed worklist (nwork2 <= N_NODES)
    {
        int blocks = (N_NODES + SPMM_WPB - 1) / SPMM_WPB;
        k_spmm1<<<blocks, SPMM_THREADS>>>((const float2*)user_emb0,
                                          (const float2*)item_emb0);
    }
    // (6) layer-2 SpMM over query worklist
    k_spmm_l3<<<(MAX_Q * 32 + 255) / 256, 256>>>((const float2*)user_emb0,
                                                 (const float2*)item_emb0);
    // (7) readout
    k_epilogue<<<(B * 32 + 255) / 256, 256>>>(users, items, user_emb, item_emb,
                                              out, B);
}

// round 17
// speedup vs baseline: 1.1173x; 1.0649x over previous
#include <cuda_runtime.h>
#include <cuda_fp16.h>
#include <cstdint>

// ---------------------------------------------------------------------------
// VS_LightGCN: 3-layer LightGCN propagation + dot-product readout.
//   N = 300000, D = 64, NNZ = 5e6, ALPHA = 0.5
//   Ek = SpMM(A, E_{k-1}) + 0.5*emb0     (E0 = cat(user_emb, item_emb))
//   light = (E0 + 3E1 + 2E2 + E3)/4 ;  gamma[b] = <light[u], light[N_USERS+i]>
//
// R17: L2 cache-policy segregation — evict_last on embedding-table gathers,
// streaming (evict-first) on edge/COO loads and layer outputs. 256-thread
// SpMM blocks (R14), packed layer-1 worklist (R16), bucket scatter (R14).
// ---------------------------------------------------------------------------

#define N_USERS 100000
#define N_ITEMS 200000
#define N_NODES (N_USERS + N_ITEMS)
#define DIM     64
#define DIMH2   32           // half2 / float2 chunks per row
#define MAX_Q   8192         // max unique query rows (2*B)
#define CAP     64           // bucket capacity per row (P(deg>64) ~ 0)
#define CAPSH   6            // log2(CAP)

// ---- static device scratch (no allocations allowed) -----------------------
__device__ __half g_H0[(size_t)N_NODES * DIM];   // fp16 concat(E0)
__device__ __half g_H1[(size_t)N_NODES * DIM];   // fp16 E1 (layer-1 gather)
__device__ __half g_H2[(size_t)N_NODES * DIM];   // fp16 E2 (layer-2 gather)
__device__ float  g_F1[MAX_Q * DIM];             // fp32 E1 at query rows
__device__ float  g_F2[MAX_Q * DIM];             // fp32 E2 at query rows
__device__ float  g_F3[MAX_Q * DIM];             // fp32 E3 at query rows
__device__ int   g_cnt[N_NODES];                 // per-row edge count
__device__ int2  g_edge[(size_t)N_NODES * CAP];  // bucketed {col, bits(val)}
__device__ int   g_flag2[N_NODES];               // E2-needed (atomicExch dedup)
__device__ int   g_flag3[N_NODES];               // query rows (atomicExch)
__device__ int   g_slot3[N_NODES];               // row -> compact F slot
__device__ int   g_work3[MAX_Q];                 // compact list of query rows
__device__ int   g_nwork3;
__device__ int   g_work2[N_NODES];               // compact list of E2 rows
__device__ int   g_nwork2;

// ---------------------------------------------------------------------------
// L2 policy helpers: pin gather tables (evict_last), stream everything else.
// ---------------------------------------------------------------------------
__device__ __forceinline__ uint64_t mk_policy_el()
{
    uint64_t pol;
    asm("createpolicy.fractional.L2::evict_last.b64 %0, 1.0;" : "=l"(pol));
    return pol;
}

__device__ __forceinline__ __half2 ldg_el_h2(const __half2* p, uint64_t pol)
{
    unsigned r;
    asm("ld.global.nc.L2::cache_hint.b32 %0,[%1],%2;"
        : "=r"(r) : "l"(p), "l"(pol));
    return *reinterpret_cast<__half2*>(&r);
}

// ---------------------------------------------------------------------------
// 0) fused: convert fp32 concat -> fp16 g_H0  AND  zero counters/flags.
// ---------------------------------------------------------------------------
__global__ void k_convert_zero(const float2* __restrict__ ue,
                               const float2* __restrict__ ie)
{
    int j = blockIdx.x * blockDim.x + threadIdx.x;
    const int total = N_NODES * DIMH2;      // 9.6M
    if (j < total) {
        int n = j >> 5;                      // node (DIMH2 == 32)
        float2 v = (n < N_USERS) ? __ldcs(&ue[j])
                                 : __ldcs(&ie[j - N_USERS * DIMH2]);
        reinterpret_cast<__half2*>(g_H0)[j] = __float22half2_rn(v);
    }
    if (j < N_NODES) {
        g_cnt[j]   = 0;
        g_flag2[j] = 0;
        g_flag3[j] = 0;
    }
    if (j == 0) { g_nwork3 = 0; g_nwork2 = 0; }
}

// ---------------------------------------------------------------------------
// 1) mark query nodes: flag3 worklist (F slots) + seed the E2 worklist
// ---------------------------------------------------------------------------
__global__ void k_mark_queries(const int* __restrict__ users,
                               const int* __restrict__ items, int B)
{
    int b = blockIdx.x * blockDim.x + threadIdx.x;
    if (b >= B) return;
    int u = __ldg(users + b);
    int i = N_USERS + __ldg(items + b);
    if (atomicExch(&g_flag3[u], 1) == 0) {
        int p = atomicAdd(&g_nwork3, 1);
        g_work3[p] = u;
        g_slot3[u] = p;
    }
    if (atomicExch(&g_flag3[i], 1) == 0) {
        int p = atomicAdd(&g_nwork3, 1);
        g_work3[p] = i;
        g_slot3[i] = p;
    }
    if (atomicExch(&g_flag2[u], 1) == 0)
        g_work2[atomicAdd(&g_nwork2, 1)] = u;
    if (atomicExch(&g_flag2[i], 1) == 0)
        g_work2[atomicAdd(&g_nwork2, 1)] = i;
}

// ---------------------------------------------------------------------------
// 2) scatter edges into fixed-capacity row buckets (4 edges/thread).
//    COO inputs are read exactly once -> streaming loads.
// ---------------------------------------------------------------------------
__global__ void k_scatter(const int*   __restrict__ rows,
                          const int*   __restrict__ cols,
                          const float* __restrict__ vals, int nnz)
{
    int t = blockIdx.x * blockDim.x + threadIdx.x;
    int e0 = t * 4;
    if (e0 + 3 < nnz) {
        int4   r = __ldcs((const int4*)(rows + e0));
        int4   c = __ldcs((const int4*)(cols + e0));
        float4 v = __ldcs((const float4*)(vals + e0));
        int p0 = atomicAdd(&g_cnt[r.x], 1);
        int p1 = atomicAdd(&g_cnt[r.y], 1);
        int p2 = atomicAdd(&g_cnt[r.z], 1);
        int p3 = atomicAdd(&g_cnt[r.w], 1);
        if (p0 < CAP) g_edge[((size_t)r.x << CAPSH) + p0] = make_int2(c.x, __float_as_int(v.x));
        if (p1 < CAP) g_edge[((size_t)r.y << CAPSH) + p1] = make_int2(c.y, __float_as_int(v.y));
        if (p2 < CAP) g_edge[((size_t)r.z << CAPSH) + p2] = make_int2(c.z, __float_as_int(v.z));
        if (p3 < CAP) g_edge[((size_t)r.w << CAPSH) + p3] = make_int2(c.w, __float_as_int(v.w));
    } else {
        for (int e = e0; e < nnz; e++) {
            int r = rows[e];
            int p = atomicAdd(&g_cnt[r], 1);
            if (p < CAP)
                g_edge[((size_t)r << CAPSH) + p] =
                    make_int2(cols[e], __float_as_int(vals[e]));
        }
    }
}

// ---------------------------------------------------------------------------
// 3) Row-parallel SpMM core: warp per row, lane owns one half2 of D.
//    fp16 gather (evict_last pinned), fp32 accumulate, 2-edge unroll.
//    Edge stream uses evict-first loads.
// ---------------------------------------------------------------------------
template <int LAYER>
__device__ __forceinline__ float2 spmm_row(int row, int lane, uint64_t pol,
                                           const float2* __restrict__ ue0,
                                           const float2* __restrict__ ie0)
{
    const __half2* in = reinterpret_cast<const __half2*>(
        (LAYER == 0) ? g_H0 : (LAYER == 1) ? g_H1 : g_H2);

    const int2* ep = g_edge + ((size_t)row << CAPSH);
    int cnt = __ldg(&g_cnt[row]);
    cnt = (cnt > CAP) ? CAP : cnt;

    float2 r0 = (row < N_USERS)
        ? __ldg(&ue0[(size_t)row * DIMH2 + lane])
        : __ldg(&ie0[(size_t)(row - N_USERS) * DIMH2 + lane]);
    float2 acc0 = make_float2(0.5f * r0.x, 0.5f * r0.y);
    float2 acc1 = make_float2(0.0f, 0.0f);

    int j = 0;
    for (; j + 2 <= cnt; j += 2) {
        int2 e0 = __ldcs(ep + j);
        int2 e1 = __ldcs(ep + j + 1);
        float2 g0 = __half22float2(ldg_el_h2(in + (size_t)e0.x * DIMH2 + lane, pol));
        float2 g1 = __half22float2(ldg_el_h2(in + (size_t)e1.x * DIMH2 + lane, pol));
        float v0 = __int_as_float(e0.y);
        float v1 = __int_as_float(e1.y);
        acc0.x = fmaf(v0, g0.x, acc0.x);
        acc0.y = fmaf(v0, g0.y, acc0.y);
        acc1.x = fmaf(v1, g1.x, acc1.x);
        acc1.y = fmaf(v1, g1.y, acc1.y);
    }
    if (j < cnt) {
        int2 e0 = __ldcs(ep + j);
        float2 g0 = __half22float2(ldg_el_h2(in + (size_t)e0.x * DIMH2 + lane, pol));
        float v0 = __int_as_float(e0.y);
        acc0.x = fmaf(v0, g0.x, acc0.x);
        acc0.y = fmaf(v0, g0.y, acc0.y);
    }
    acc0.x += acc1.x;
    acc0.y += acc1.y;
    return acc0;
}

// Layer 0: all rows -> H1 (+F1 at query rows). 256-thread blocks (R14-proven).
__global__ void __launch_bounds__(256)
k_spmm0(const float2* __restrict__ ue0, const float2* __restrict__ ie0)
{
    int w    = (blockIdx.x * blockDim.x + threadIdx.x) >> 5;
    int lane = threadIdx.x & 31;
    if (w >= N_NODES) return;

    uint64_t pol = mk_policy_el();
    float2 acc = spmm_row<0>(w, lane, pol, ue0, ie0);

    __stcs(reinterpret_cast<__half2*>(g_H1) + (size_t)w * DIMH2 + lane,
           __float22half2_rn(acc));
    if (g_flag3[w]) {
        reinterpret_cast<float2*>(g_F1)[(size_t)g_slot3[w] * DIMH2 + lane] = acc;
    }
}

// ---------------------------------------------------------------------------
// 4) extend E2 worklist with in-neighbors of query rows (dedup).
// ---------------------------------------------------------------------------
__global__ void k_flag2()
{
    int w    = (blockIdx.x * blockDim.x + threadIdx.x) >> 5;
    int lane = threadIdx.x & 31;
    if (w >= g_nwork3) return;
    int row = g_work3[w];
    int cnt = __ldg(&g_cnt[row]);
    cnt = (cnt > CAP) ? CAP : cnt;
    const int2* ep = g_edge + ((size_t)row << CAPSH);
    for (int j = lane; j < cnt; j += 32) {
        int c = ep[j].x;
        if (atomicExch(&g_flag2[c], 1) == 0)
            g_work2[atomicAdd(&g_nwork2, 1)] = c;
    }
}

// Layer 1: packed worklist rows -> H2 (+F2 at query rows). 256-thread blocks.
__global__ void __launch_bounds__(256)
k_spmm1(const float2* __restrict__ ue0, const float2* __restrict__ ie0)
{
    int w    = (blockIdx.x * blockDim.x + threadIdx.x) >> 5;
    int lane = threadIdx.x & 31;
    if (w >= g_nwork2) return;
    int row = g_work2[w];

    uint64_t pol = mk_policy_el();
    float2 acc = spmm_row<1>(row, lane, pol, ue0, ie0);

    __stcs(reinterpret_cast<__half2*>(g_H2) + (size_t)row * DIMH2 + lane,
           __float22half2_rn(acc));
    if (g_flag3[row]) {
        reinterpret_cast<float2*>(g_F2)[(size_t)g_slot3[row] * DIMH2 + lane] = acc;
    }
}

// Layer 2 over the query worklist (<= MAX_Q rows); fp32 output only.
__global__ void __launch_bounds__(256)
k_spmm_l3(const float2* __restrict__ ue0, const float2* __restrict__ ie0)
{
    int w    = (blockIdx.x * blockDim.x + threadIdx.x) >> 5;
    int lane = threadIdx.x & 31;
    if (w >= g_nwork3) return;
    int row = g_work3[w];
    uint64_t pol = mk_policy_el();
    float2 acc = spmm_row<2>(row, lane, pol, ue0, ie0);
    reinterpret_cast<float2*>(g_F3)[(size_t)w * DIMH2 + lane] = acc;  // slot == w
}

// ---------------------------------------------------------------------------
// 5) Epilogue: warp per output b. All reads fp32 (E0 tables + compact F1..F3).
// ---------------------------------------------------------------------------
__global__ void k_epilogue(const int* __restrict__ users,
                           const int* __restrict__ items,
                           const float* __restrict__ user_emb,
                           const float* __restrict__ item_emb,
                           float* __restrict__ out, int B)
{
    int t = blockIdx.x * blockDim.x + threadIdx.x;
    int b = t >> 5;
    int lane = t & 31;
    if (b >= B) return;

    int u = __ldg(users + b);
    int i = N_USERS + __ldg(items + b);
    int su = __ldg(&g_slot3[u]);
    int si = __ldg(&g_slot3[i]);

    float s = 0.0f;
#pragma unroll
    for (int k = 0; k < 2; k++) {
        int d = lane + 32 * k;
        size_t uo = (size_t)su * DIM + d;
        size_t io = (size_t)si * DIM + d;

        float cu = user_emb[(size_t)u * DIM + d];   // u always < N_USERS
        float ci = item_emb[(size_t)(i - N_USERS) * DIM + d];

        float lu = (cu + 3.0f * g_F1[uo] + 2.0f * g_F2[uo] + g_F3[uo]) * 0.25f;
        float li = (ci + 3.0f * g_F1[io] + 2.0f * g_F2[io] + g_F3[io]) * 0.25f;
        s = fmaf(lu, li, s);
    }
#pragma unroll
    for (int o = 16; o > 0; o >>= 1)
        s += __shfl_xor_sync(0xffffffffu, s, o);
    if (lane == 0) out[b] = s;
}

// ---------------------------------------------------------------------------
// kernel_launch — stream-ordered, graph-capturable, allocation-free.
// Order: (0) convert_zero (1) mark (2) scatter (3) spmm0 <- profiled index
//        (4) flag2 (5) spmm1 (6) spmm_l3 (7) epilogue
// Inputs: users, items, rows, cols, vals, user_emb, item_emb, user_emb0, item_emb0
// ---------------------------------------------------------------------------
extern "C" void kernel_launch(void* const* d_in, const int* in_sizes, int n_in,
                              void* d_out, int out_size)
{
    const int*   users     = (const int*)  d_in[0];
    const int*   items     = (const int*)  d_in[1];
    const int*   rows      = (const int*)  d_in[2];
    const int*   cols      = (const int*)  d_in[3];
    const float* vals      = (const float*)d_in[4];
    const float* user_emb  = (const float*)d_in[5];
    const float* item_emb  = (const float*)d_in[6];
    const float* user_emb0 = (const float*)d_in[7];
    const float* item_emb0 = (const float*)d_in[8];
    float*       out       = (float*)d_out;

    const int nnz = in_sizes[2];
    const int B   = in_sizes[0];

    // (0) fused convert + zero
    {
        int total = N_NODES * DIMH2;
        k_convert_zero<<<(total + 255) / 256, 256>>>((const float2*)user_emb,
                                                     (const float2*)item_emb);
    }
    // (1) mark queries (seeds work2 + work3)
    k_mark_queries<<<(B + 255) / 256, 256>>>(users, items, B);
    // (2) bucket scatter (builds counts too)
    {
        int nt4 = (nnz + 3) / 4;
        k_scatter<<<(nt4 + 255) / 256, 256>>>(rows, cols, vals, nnz);
    }
    // (3) layer-0 SpMM  <- ncu profiled launch
    {
        int blocks = (N_NODES + 7) / 8;
        k_spmm0<<<blocks, 256>>>((const float2*)user_emb0,
                                 (const float2*)item_emb0);
    }
    // (4) extend E2 worklist with query-row neighbors
    k_flag2<<<(MAX_Q * 32 + 255) / 256, 256>>>();
    // (5) layer-1 SpMM over packed worklist
    {
        int blocks = (N_NODES + 7) / 8;
        k_spmm1<<<blocks, 256>>>((const float2*)user_emb0,
                                 (const float2*)item_emb0);
    }
    // (6) layer-2 SpMM over query worklist
    k_spmm_l3<<<(MAX_Q * 32 + 255) / 256, 256>>>((const float2*)user_emb0,
                                                 (const float2*)item_emb0);
    // (7) readout
    k_epilogue<<<(B * 32 + 255) / 256, 256>>>(users, items, user_emb, item_emb,
                                              out, B);
}